// round 2
// baseline (speedup 1.0000x reference)
#include <cuda_runtime.h>
#include <cuda_bf16.h>
#include <stdint.h>
#include <math.h>

#define H      1024
#define O_DIM  8192
#define T_STEPS 64
#define B_SZ   256
#define BH     (B_SZ * H)
#define K2     (2 * H)
#define BKP    40

// ---- device scratch (static; ~120 MB) ----
__device__ __nv_bfloat16 g_Wcat_hi[2 * H * K2];
__device__ __nv_bfloat16 g_Wcat_lo[2 * H * K2];
__device__ __nv_bfloat16 g_fcW_hi[O_DIM * H];
__device__ __nv_bfloat16 g_fcW_lo[O_DIM * H];
__device__ __nv_bfloat16 g_outs_hi[(T_STEPS + 1) * BH];
__device__ __nv_bfloat16 g_outs_lo[(T_STEPS + 1) * BH];
__device__ __nv_bfloat16 g_h0_hi[2 * BH];
__device__ __nv_bfloat16 g_h0_lo[2 * BH];
__device__ __nv_bfloat16 g_h1i_hi[BH];
__device__ __nv_bfloat16 g_h1i_lo[BH];

__device__ __forceinline__ void split2(float v, __nv_bfloat16 &hi, __nv_bfloat16 &lo) {
    hi = __float2bfloat16(v);
    lo = __float2bfloat16(v - __bfloat162float(hi));
}

// ---- prep kernels ----
__global__ void prep_wcat_kernel(const float* __restrict__ W_ih,
                                 const float* __restrict__ W_hh) {
    int idx = blockIdx.x * blockDim.x + threadIdx.x;
    if (idx >= 2 * H * K2) return;
    int l = idx / (H * K2);
    int rem = idx - l * (H * K2);
    int n = rem / K2, k = rem - n * K2;
    float w = (k < H) ? W_ih[(l * H + n) * H + k] : W_hh[(l * H + n) * H + (k - H)];
    split2(w, g_Wcat_hi[idx], g_Wcat_lo[idx]);
}
__global__ void prep_fcw_kernel(const float* __restrict__ fcW) {
    int idx = blockIdx.x * blockDim.x + threadIdx.x;
    if (idx >= O_DIM * H) return;
    split2(fcW[idx], g_fcW_hi[idx], g_fcW_lo[idx]);
}
__global__ void prep_acts_kernel(const float* __restrict__ x,
                                 const float* __restrict__ hidden) {
    int idx = blockIdx.x * blockDim.x + threadIdx.x;
    if (idx >= 3 * BH) return;
    if (idx < BH)            split2(x[idx], g_outs_hi[idx], g_outs_lo[idx]);
    else if (idx < 2 * BH) { int j = idx - BH;     split2(hidden[j],      g_h0_hi[j],  g_h0_lo[j]); }
    else                   { int j = idx - 2 * BH; split2(hidden[BH + j], g_h1i_hi[j], g_h1i_lo[j]); }
}

// ---- helpers ----
__device__ __forceinline__ void cpasync16(void* dst, const void* src) {
    uint32_t d = (uint32_t)__cvta_generic_to_shared(dst);
    asm volatile("cp.async.cg.shared.global [%0], [%1], 16;" :: "r"(d), "l"(src));
}
__device__ __forceinline__ void cp_commit() { asm volatile("cp.async.commit_group;"); }
template <int N> __device__ __forceinline__ void cp_wait() {
    asm volatile("cp.async.wait_group %0;" :: "n"(N));
}
__device__ __forceinline__ uint32_t lds32(const __nv_bfloat16* p) {
    return *reinterpret_cast<const uint32_t*>(p);
}
__device__ __forceinline__ void mma_bf16(float* c, const uint32_t* a, const uint32_t* b) {
    asm volatile(
        "mma.sync.aligned.m16n8k16.row.col.f32.bf16.bf16.f32 "
        "{%0,%1,%2,%3}, {%4,%5,%6,%7}, {%8,%9}, {%0,%1,%2,%3};"
        : "+f"(c[0]), "+f"(c[1]), "+f"(c[2]), "+f"(c[3])
        : "r"(a[0]), "r"(a[1]), "r"(a[2]), "r"(a[3]), "r"(b[0]), "r"(b[1]));
}

// ---- RNN layer step: C = tanh([A1|A2] @ Wcat^T + b1 + b2), M=256,N=1024,K=2048
// tile 64x64, BK=32, 128 thr (2x2 warps, warp 32x32), split-bf16 3-pass
__global__ __launch_bounds__(128) void rnn_step_kernel(
    const __nv_bfloat16* __restrict__ A1h, const __nv_bfloat16* __restrict__ A1l,
    const __nv_bfloat16* __restrict__ A2h, const __nv_bfloat16* __restrict__ A2l,
    const __nv_bfloat16* __restrict__ Bh,  const __nv_bfloat16* __restrict__ Bl,
    const float* __restrict__ bias1, const float* __restrict__ bias2,
    __nv_bfloat16* __restrict__ Ch, __nv_bfloat16* __restrict__ Cl)
{
    __shared__ __align__(16) __nv_bfloat16 sA[4][64 * BKP];
    __shared__ __align__(16) __nv_bfloat16 sB[4][64 * BKP];
    const int tid = threadIdx.x;
    const int by64 = blockIdx.y * 64, bx64 = blockIdx.x * 64;

    auto prefetch = [&](int kc, int st) {
        const bool lowk = (kc < 32);
        const int k0 = (lowk ? kc : kc - 32) * 32;
        const __nv_bfloat16* Ah = lowk ? A1h : A2h;
        const __nv_bfloat16* Al = lowk ? A1l : A2l;
        #pragma unroll
        for (int i = 0; i < 4; i++) {
            int slot = i * 128 + tid;
            int half = slot >> 8, rem = slot & 255;
            int r = rem >> 2, c = (rem & 3) * 8;
            cpasync16(&sA[st * 2 + half][r * BKP + c],
                      (half ? Al : Ah) + (by64 + r) * H + k0 + c);
        }
        const int kb = kc * 32;
        #pragma unroll
        for (int i = 0; i < 4; i++) {
            int slot = i * 128 + tid;
            int half = slot >> 8, rem = slot & 255;
            int r = rem >> 2, c = (rem & 3) * 8;
            cpasync16(&sB[st * 2 + half][r * BKP + c],
                      (half ? Bl : Bh) + (bx64 + r) * K2 + kb + c);
        }
    };

    float acc[2][4][4];
    #pragma unroll
    for (int mt = 0; mt < 2; mt++)
        #pragma unroll
        for (int nt = 0; nt < 4; nt++)
            #pragma unroll
            for (int i = 0; i < 4; i++) acc[mt][nt][i] = 0.f;

    const int lane = tid & 31, wid = tid >> 5;
    const int g = lane >> 2, tg = lane & 3;
    const int wm = wid >> 1, wn = wid & 1;

    prefetch(0, 0); cp_commit();
    for (int kc = 0; kc < 64; kc++) {
        int st = kc & 1;
        if (kc + 1 < 64) { prefetch(kc + 1, st ^ 1); cp_commit(); cp_wait<1>(); }
        else             { cp_wait<0>(); }
        __syncthreads();
        const __nv_bfloat16* pAh = sA[st * 2 + 0];
        const __nv_bfloat16* pAl = sA[st * 2 + 1];
        const __nv_bfloat16* pBh = sB[st * 2 + 0];
        const __nv_bfloat16* pBl = sB[st * 2 + 1];
        #pragma unroll
        for (int kk = 0; kk < 2; kk++) {
            const int c0 = kk * 16 + tg * 2;
            uint32_t afh[2][4], afl[2][4];
            #pragma unroll
            for (int mt = 0; mt < 2; mt++) {
                int r = wm * 32 + mt * 16 + g;
                afh[mt][0] = lds32(pAh + r * BKP + c0);
                afh[mt][1] = lds32(pAh + (r + 8) * BKP + c0);
                afh[mt][2] = lds32(pAh + r * BKP + c0 + 8);
                afh[mt][3] = lds32(pAh + (r + 8) * BKP + c0 + 8);
                afl[mt][0] = lds32(pAl + r * BKP + c0);
                afl[mt][1] = lds32(pAl + (r + 8) * BKP + c0);
                afl[mt][2] = lds32(pAl + r * BKP + c0 + 8);
                afl[mt][3] = lds32(pAl + (r + 8) * BKP + c0 + 8);
            }
            #pragma unroll
            for (int nt = 0; nt < 4; nt++) {
                int n = wn * 32 + nt * 8 + g;
                uint32_t bh[2] = { lds32(pBh + n * BKP + c0), lds32(pBh + n * BKP + c0 + 8) };
                uint32_t bl[2] = { lds32(pBl + n * BKP + c0), lds32(pBl + n * BKP + c0 + 8) };
                #pragma unroll
                for (int mt = 0; mt < 2; mt++) {
                    mma_bf16(acc[mt][nt], afh[mt], bh);
                    mma_bf16(acc[mt][nt], afl[mt], bh);
                    mma_bf16(acc[mt][nt], afh[mt], bl);
                }
            }
        }
        __syncthreads();
    }

    #pragma unroll
    for (int mt = 0; mt < 2; mt++) {
        #pragma unroll
        for (int nt = 0; nt < 4; nt++) {
            int r = by64 + wm * 32 + mt * 16 + g;
            int cidx = bx64 + wn * 32 + nt * 8 + tg * 2;
            float bb0 = bias1[cidx] + bias2[cidx];
            float bb1 = bias1[cidx + 1] + bias2[cidx + 1];
            float v0 = tanhf(acc[mt][nt][0] + bb0);
            float v1 = tanhf(acc[mt][nt][1] + bb1);
            float v2 = tanhf(acc[mt][nt][2] + bb0);
            float v3 = tanhf(acc[mt][nt][3] + bb1);
            __nv_bfloat16 h0, l0, h1, l1; __nv_bfloat162 t;
            split2(v0, h0, l0); split2(v1, h1, l1);
            t.x = h0; t.y = h1; *reinterpret_cast<__nv_bfloat162*>(&Ch[r * H + cidx]) = t;
            t.x = l0; t.y = l1; *reinterpret_cast<__nv_bfloat162*>(&Cl[r * H + cidx]) = t;
            split2(v2, h0, l0); split2(v3, h1, l1);
            t.x = h0; t.y = h1; *reinterpret_cast<__nv_bfloat162*>(&Ch[(r + 8) * H + cidx]) = t;
            t.x = l0; t.y = l1; *reinterpret_cast<__nv_bfloat162*>(&Cl[(r + 8) * H + cidx]) = t;
        }
    }
}

// ---- FC: out = A @ fcW^T + fc_b ; M=16384,N=8192,K=1024
// tile 128x128, BK=32, 256 thr (2x4 warps, warp 64x32), dynamic smem 80KB
#define FC_TILE (128 * BKP)
__global__ __launch_bounds__(256) void fc_kernel(
    const __nv_bfloat16* __restrict__ Ah, const __nv_bfloat16* __restrict__ Al,
    const __nv_bfloat16* __restrict__ Bh, const __nv_bfloat16* __restrict__ Bl,
    const float* __restrict__ fcb, float* __restrict__ outp)
{
    extern __shared__ __align__(16) __nv_bfloat16 smem[];
    __nv_bfloat16* sA = smem;
    __nv_bfloat16* sB = smem + 4 * FC_TILE;
    const int tid = threadIdx.x;
    const int row0 = blockIdx.y * 128, col0 = blockIdx.x * 128;

    auto prefetch = [&](int kc, int st) {
        const int k0 = kc * 32;
        #pragma unroll
        for (int i = 0; i < 8; i++) {
            int slot = i * 256 + tid;
            int mat = slot >> 9;
            int rem = slot & 511;
            int r = rem >> 2, c = (rem & 3) * 8;
            const __nv_bfloat16* src; __nv_bfloat16* dst;
            if (mat < 2) {
                src = (mat ? Al : Ah) + (size_t)(row0 + r) * H + k0 + c;
                dst = sA + (st * 2 + mat) * FC_TILE + r * BKP + c;
            } else {
                src = ((mat == 3) ? Bl : Bh) + (size_t)(col0 + r) * H + k0 + c;
                dst = sB + (st * 2 + (mat - 2)) * FC_TILE + r * BKP + c;
            }
            cpasync16(dst, src);
        }
    };

    float acc[4][4][4];
    #pragma unroll
    for (int mt = 0; mt < 4; mt++)
        #pragma unroll
        for (int nt = 0; nt < 4; nt++)
            #pragma unroll
            for (int i = 0; i < 4; i++) acc[mt][nt][i] = 0.f;

    const int lane = tid & 31, wid = tid >> 5;
    const int g = lane >> 2, tg = lane & 3;
    const int wm = wid >> 2, wn = wid & 3;

    prefetch(0, 0); cp_commit();
    for (int kc = 0; kc < 32; kc++) {
        int st = kc & 1;
        if (kc + 1 < 32) { prefetch(kc + 1, st ^ 1); cp_commit(); cp_wait<1>(); }
        else             { cp_wait<0>(); }
        __syncthreads();
        const __nv_bfloat16* pAh = sA + (st * 2 + 0) * FC_TILE;
        const __nv_bfloat16* pAl = sA + (st * 2 + 1) * FC_TILE;
        const __nv_bfloat16* pBh = sB + (st * 2 + 0) * FC_TILE;
        const __nv_bfloat16* pBl = sB + (st * 2 + 1) * FC_TILE;
        #pragma unroll
        for (int kk = 0; kk < 2; kk++) {
            const int c0 = kk * 16 + tg * 2;
            uint32_t afh[4][4], afl[4][4];
            #pragma unroll
            for (int mt = 0; mt < 4; mt++) {
                int r = wm * 64 + mt * 16 + g;
                afh[mt][0] = lds32(pAh + r * BKP + c0);
                afh[mt][1] = lds32(pAh + (r + 8) * BKP + c0);
                afh[mt][2] = lds32(pAh + r * BKP + c0 + 8);
                afh[mt][3] = lds32(pAh + (r + 8) * BKP + c0 + 8);
                afl[mt][0] = lds32(pAl + r * BKP + c0);
                afl[mt][1] = lds32(pAl + (r + 8) * BKP + c0);
                afl[mt][2] = lds32(pAl + r * BKP + c0 + 8);
                afl[mt][3] = lds32(pAl + (r + 8) * BKP + c0 + 8);
            }
            #pragma unroll
            for (int nt = 0; nt < 4; nt++) {
                int n = wn * 32 + nt * 8 + g;
                uint32_t bh[2] = { lds32(pBh + n * BKP + c0), lds32(pBh + n * BKP + c0 + 8) };
                uint32_t bl[2] = { lds32(pBl + n * BKP + c0), lds32(pBl + n * BKP + c0 + 8) };
                #pragma unroll
                for (int mt = 0; mt < 4; mt++) {
                    mma_bf16(acc[mt][nt], afh[mt], bh);
                    mma_bf16(acc[mt][nt], afl[mt], bh);
                    mma_bf16(acc[mt][nt], afh[mt], bl);
                }
            }
        }
        __syncthreads();
    }

    #pragma unroll
    for (int mt = 0; mt < 4; mt++) {
        #pragma unroll
        for (int nt = 0; nt < 4; nt++) {
            size_t r = row0 + wm * 64 + mt * 16 + g;
            int cidx = col0 + wn * 32 + nt * 8 + tg * 2;
            float b0 = fcb[cidx], b1 = fcb[cidx + 1];
            float2 p0 = { acc[mt][nt][0] + b0, acc[mt][nt][1] + b1 };
            float2 p1 = { acc[mt][nt][2] + b0, acc[mt][nt][3] + b1 };
            *reinterpret_cast<float2*>(&outp[r * O_DIM + cidx]) = p0;
            *reinterpret_cast<float2*>(&outp[(r + 8) * O_DIM + cidx]) = p1;
        }
    }
}

// ---- host launcher ----
extern "C" void kernel_launch(void* const* d_in, const int* in_sizes, int n_in,
                              void* d_out, int out_size) {
    const float* x      = (const float*)d_in[0];
    const float* hidden = (const float*)d_in[1];
    const float* W_ih   = (const float*)d_in[3];
    const float* W_hh   = (const float*)d_in[4];
    const float* b_ih   = (const float*)d_in[5];
    const float* b_hh   = (const float*)d_in[6];
    const float* fc_W   = (const float*)d_in[7];
    const float* fc_b   = (const float*)d_in[8];
    float* outp = (float*)d_out;

    __nv_bfloat16 *Wh, *Wl, *Fh, *Fl, *Oh, *Ol, *H0h, *H0l, *H1h, *H1l;
    cudaGetSymbolAddress((void**)&Wh,  g_Wcat_hi);
    cudaGetSymbolAddress((void**)&Wl,  g_Wcat_lo);
    cudaGetSymbolAddress((void**)&Fh,  g_fcW_hi);
    cudaGetSymbolAddress((void**)&Fl,  g_fcW_lo);
    cudaGetSymbolAddress((void**)&Oh,  g_outs_hi);
    cudaGetSymbolAddress((void**)&Ol,  g_outs_lo);
    cudaGetSymbolAddress((void**)&H0h, g_h0_hi);
    cudaGetSymbolAddress((void**)&H0l, g_h0_lo);
    cudaGetSymbolAddress((void**)&H1h, g_h1i_hi);
    cudaGetSymbolAddress((void**)&H1l, g_h1i_lo);

    prep_wcat_kernel<<<(2 * H * K2 + 255) / 256, 256>>>(W_ih, W_hh);
    prep_fcw_kernel<<<(O_DIM * H + 255) / 256, 256>>>(fc_W);
    prep_acts_kernel<<<(3 * BH + 255) / 256, 256>>>(x, hidden);

    dim3 rgrid(H / 64, B_SZ / 64);   // (16, 4)
    int p = 0;
    for (int t = 0; t < T_STEPS; t++) {
        // layer 0: in = outs[t], h = h0[p] -> h0[p^1]
        rnn_step_kernel<<<rgrid, 128>>>(
            Oh + (size_t)t * BH, Ol + (size_t)t * BH,
            H0h + (size_t)p * BH, H0l + (size_t)p * BH,
            Wh, Wl, b_ih, b_hh,
            H0h + (size_t)(p ^ 1) * BH, H0l + (size_t)(p ^ 1) * BH);
        // layer 1: in = h0[p^1], h = (t==0 ? h1i : outs[t]) -> outs[t+1]
        const __nv_bfloat16* h1h = (t == 0) ? H1h : Oh + (size_t)t * BH;
        const __nv_bfloat16* h1l = (t == 0) ? H1l : Ol + (size_t)t * BH;
        rnn_step_kernel<<<rgrid, 128>>>(
            H0h + (size_t)(p ^ 1) * BH, H0l + (size_t)(p ^ 1) * BH,
            h1h, h1l,
            Wh + (size_t)H * K2, Wl + (size_t)H * K2, b_ih + H, b_hh + H,
            Oh + (size_t)(t + 1) * BH, Ol + (size_t)(t + 1) * BH);
        p ^= 1;
    }

    size_t fc_smem = 8 * FC_TILE * sizeof(__nv_bfloat16);  // 81920 B
    cudaFuncSetAttribute(fc_kernel, cudaFuncAttributeMaxDynamicSharedMemorySize,
                         (int)fc_smem);
    dim3 fgrid(O_DIM / 128, (T_STEPS * B_SZ) / 128);  // (64, 128)
    fc_kernel<<<fgrid, 256, fc_smem>>>(
        Oh + BH, Ol + BH, Fh, Fl, fc_b, outp);
}